// round 10
// baseline (speedup 1.0000x reference)
#include <cuda_runtime.h>

#define NSETS 8
#define NPTS  4096
#define DF    16
#define KK    16
#define QT    128                 // threads per block
#define RQ    2                   // queries per thread
#define QB    (QT * RQ)           // queries per block = 256
#define CT    128                 // candidate tile size
#define SPLIT 4                   // candidate-range splits
#define CPS   (NPTS / SPLIT)      // candidates per split = 1024
#define NQ    (NSETS * NPTS)      // total queries = 32768
#define BUFN  12                  // per-thread append buffer slots
#define FLUSH_AT 8                // flush when cnt >= 8 (4 slots slack, vote every 4)

typedef unsigned long long u64;
typedef unsigned int u32;

// ---- device scratch for partial top-k (no allocs allowed) ----
__device__ float g_partD[NQ * SPLIT * KK];
__device__ int   g_partI[NQ * SPLIT * KK];

// ---- packed f32x2 helpers (two fp32 lanes per instruction, exact) ----
__device__ __forceinline__ u64 f2mul(u64 a, u64 b) {
    u64 d; asm("mul.rn.f32x2 %0, %1, %2;" : "=l"(d) : "l"(a), "l"(b)); return d;
}
__device__ __forceinline__ u64 f2fma(u64 a, u64 b, u64 c) {
    u64 d; asm("fma.rn.f32x2 %0, %1, %2, %3;" : "=l"(d) : "l"(a), "l"(b), "l"(c)); return d;
}
__device__ __forceinline__ u64 f2add(u64 a, u64 b) {
    u64 d; asm("add.rn.f32x2 %0, %1, %2;" : "=l"(d) : "l"(a), "l"(b)); return d;
}

// 16-dim dot with a FIXED summation tree, used for norms AND cross dots so
// that self-distance cancels exactly: dot(q,q)==qn => fmaf(-2,dot,qn+cn)==0.
__device__ __forceinline__ float pdot16(const u64* a, const u64* b) {
    u64 pA = f2mul(a[0], b[0]);
    pA = f2fma(a[1], b[1], pA);
    pA = f2fma(a[2], b[2], pA);
    pA = f2fma(a[3], b[3], pA);
    u64 pB = f2mul(a[4], b[4]);
    pB = f2fma(a[5], b[5], pB);
    pB = f2fma(a[6], b[6], pB);
    pB = f2fma(a[7], b[7], pB);
    u64 pC = f2add(pA, pB);
    float lo, hi;
    asm("mov.b64 {%0, %1}, %2;" : "=f"(lo), "=f"(hi) : "l"(pC));
    return lo + hi;
}

// ============================ pass 1: partial top-k ============================
__global__ __launch_bounds__(QT) void knn_part(const float* __restrict__ x) {
    __shared__ ulonglong2 sC[CT * 4];           // candidate tile (64B/point)
    __shared__ float      sN[CT];               // candidate squared norms
    __shared__ u64        sBuf[RQ][BUFN][QT];   // per-thread append buffers

    const int set   = blockIdx.y;
    const int split = blockIdx.z;
    const int qi0   = blockIdx.x * QB + threadIdx.x;  // query 0 (lane-coalesced)
    const int qi1   = qi0 + QT;                       // query 1
    const float* xs = x + (size_t)set * NPTS * DF;

    // load both query points (packed) + norms
    u64 qA[8], qB[8];
    {
        const ulonglong2* qp = reinterpret_cast<const ulonglong2*>(xs + (size_t)qi0 * DF);
        ulonglong2 w0 = qp[0], w1 = qp[1], w2 = qp[2], w3 = qp[3];
        qA[0] = w0.x; qA[1] = w0.y; qA[2] = w1.x; qA[3] = w1.y;
        qA[4] = w2.x; qA[5] = w2.y; qA[6] = w3.x; qA[7] = w3.y;
    }
    {
        const ulonglong2* qp = reinterpret_cast<const ulonglong2*>(xs + (size_t)qi1 * DF);
        ulonglong2 w0 = qp[0], w1 = qp[1], w2 = qp[2], w3 = qp[3];
        qB[0] = w0.x; qB[1] = w0.y; qB[2] = w1.x; qB[3] = w1.y;
        qB[4] = w2.x; qB[5] = w2.y; qB[6] = w3.x; qB[7] = w3.y;
    }
    const float qnA = pdot16(qA, qA);
    const float qnB = pdot16(qB, qB);

    float bdA[KK], bdB[KK];
    int   biA[KK], biB[KK];
#pragma unroll
    for (int t = 0; t < KK; ++t) {
        bdA[t] = __int_as_float(0x7f800000);
        bdB[t] = __int_as_float(0x7f800000);
        biA[t] = 0; biB[t] = 0;
    }
    float thA = __int_as_float(0x7f800000);
    float thB = __int_as_float(0x7f800000);
    int cntA = 0, cntB = 0;

    // drain one query's buffer into its sorted top-k (rare, warp-batched)
    auto flushOne = [&](int qs, float* bd, int* bi, int& cnt, float& th) {
        for (int b = 0; b < cnt; ++b) {
            u64 key = sBuf[qs][b][threadIdx.x];
            u32 iu; float d;
            asm("mov.b64 {%0, %1}, %2;" : "=r"(iu), "=f"(d) : "l"(key));
            if (d < bd[KK - 1]) {
                const int idx = (int)iu;
#pragma unroll
                for (int t = KK - 1; t >= 1; --t) {
                    const bool shift = d < bd[t - 1];
                    const bool here  = d < bd[t];
                    bd[t] = shift ? bd[t - 1] : (here ? d : bd[t]);
                    bi[t] = shift ? bi[t - 1] : (here ? idx : bi[t]);
                }
                if (d < bd[0]) { bd[0] = d; bi[0] = idx; }
            }
        }
        cnt = 0;
        th = bd[KK - 1];
    };

    const int cbase = split * CPS;
    for (int tile = 0; tile < CPS / CT; ++tile) {
        const int cj0 = cbase + tile * CT;
        __syncthreads();
        {
            const ulonglong2* cp = reinterpret_cast<const ulonglong2*>(
                xs + (size_t)(cj0 + threadIdx.x) * DF);
            ulonglong2 w0 = cp[0], w1 = cp[1], w2 = cp[2], w3 = cp[3];
            sC[threadIdx.x * 4 + 0] = w0;
            sC[threadIdx.x * 4 + 1] = w1;
            sC[threadIdx.x * 4 + 2] = w2;
            sC[threadIdx.x * 4 + 3] = w3;
            u64 a[8] = {w0.x, w0.y, w1.x, w1.y, w2.x, w2.y, w3.x, w3.y};
            sN[threadIdx.x] = pdot16(a, a);
        }
        __syncthreads();

        for (int j0 = 0; j0 < CT; j0 += 4) {
#pragma unroll
            for (int u = 0; u < 4; ++u) {
                const int j = j0 + u;
                const ulonglong2* sp = &sC[j * 4];
                ulonglong2 w0 = sp[0], w1 = sp[1], w2 = sp[2], w3 = sp[3];
                u64 c[8] = {w0.x, w0.y, w1.x, w1.y, w2.x, w2.y, w3.x, w3.y};
                const float cn = sN[j];
                const float dA = fmaf(-2.0f, pdot16(qA, c), qnA + cn);
                const float dB = fmaf(-2.0f, pdot16(qB, c), qnB + cn);
                const int idx = cj0 + j;
                // predicated conditional appends (no store traffic on miss)
                if (dA < thA) {
                    u64 key;
                    asm("mov.b64 %0, {%1, %2};" : "=l"(key) : "r"(idx), "f"(dA));
                    sBuf[0][cntA][threadIdx.x] = key;
                    ++cntA;
                }
                if (dB < thB) {
                    u64 key;
                    asm("mov.b64 %0, {%1, %2};" : "=l"(key) : "r"(idx), "f"(dB));
                    sBuf[1][cntB][threadIdx.x] = key;
                    ++cntB;
                }
            }
            // warp-uniform check every 4 candidates (4 slots of slack)
            if (__any_sync(0xffffffffu, (cntA >= FLUSH_AT) | (cntB >= FLUSH_AT))) {
                flushOne(0, bdA, biA, cntA, thA);
                flushOne(1, bdB, biB, cntB, thB);
            }
        }
    }
    if (__any_sync(0xffffffffu, (cntA > 0) | (cntB > 0))) {
        flushOne(0, bdA, biA, cntA, thA);
        flushOne(1, bdB, biB, cntB, thB);
    }

    // write sorted partial lists
    {
        const int g0 = set * NPTS + qi0;
        float4* pd = reinterpret_cast<float4*>(&g_partD[((size_t)g0 * SPLIT + split) * KK]);
        int4*   pi = reinterpret_cast<int4*>(&g_partI[((size_t)g0 * SPLIT + split) * KK]);
#pragma unroll
        for (int t = 0; t < KK; t += 4) {
            pd[t / 4] = make_float4(bdA[t], bdA[t + 1], bdA[t + 2], bdA[t + 3]);
            pi[t / 4] = make_int4(biA[t], biA[t + 1], biA[t + 2], biA[t + 3]);
        }
    }
    {
        const int g1 = set * NPTS + qi1;
        float4* pd = reinterpret_cast<float4*>(&g_partD[((size_t)g1 * SPLIT + split) * KK]);
        int4*   pi = reinterpret_cast<int4*>(&g_partI[((size_t)g1 * SPLIT + split) * KK]);
#pragma unroll
        for (int t = 0; t < KK; t += 4) {
            pd[t / 4] = make_float4(bdB[t], bdB[t + 1], bdB[t + 2], bdB[t + 3]);
            pi[t / 4] = make_int4(biB[t], biB[t + 1], biB[t + 2], biB[t + 3]);
        }
    }
}

// ============================ pass 2: merge + emit ============================
__device__ __forceinline__ bool lex_less(float d1, int i1, float d2, int i2) {
    return (d1 < d2) || (d1 == d2 && i1 < i2);
}

__device__ __forceinline__ void merge16(const float* dA, const int* iA,
                                        const float* dB, const int* iB,
                                        float* dR, int* iR) {
#pragma unroll
    for (int i = 0; i < KK; ++i) {
        const bool ta = lex_less(dA[i], iA[i], dB[KK - 1 - i], iB[KK - 1 - i]);
        dR[i] = ta ? dA[i] : dB[KK - 1 - i];
        iR[i] = ta ? iA[i] : iB[KK - 1 - i];
    }
#pragma unroll
    for (int s = 8; s >= 1; s >>= 1) {
#pragma unroll
        for (int i = 0; i < KK; ++i) {
            if ((i & s) == 0) {
                const bool swap = !lex_less(dR[i], iR[i], dR[i + s], iR[i + s]);
                const float td = swap ? dR[i + s] : dR[i];
                const int   ti = swap ? iR[i + s] : iR[i];
                dR[i + s] = swap ? dR[i] : dR[i + s];
                iR[i + s] = swap ? iR[i] : iR[i + s];
                dR[i] = td;
                iR[i] = ti;
            }
        }
    }
}

__global__ __launch_bounds__(128) void knn_merge(float* __restrict__ out) {
    const int q = blockIdx.x * 128 + threadIdx.x;
    if (q >= NQ) return;

    float D[SPLIT][KK];
    int   I[SPLIT][KK];
#pragma unroll
    for (int s = 0; s < SPLIT; ++s) {
        const float4* pd = reinterpret_cast<const float4*>(&g_partD[((size_t)q * SPLIT + s) * KK]);
        const int4*   pi = reinterpret_cast<const int4*>(&g_partI[((size_t)q * SPLIT + s) * KK]);
#pragma unroll
        for (int t = 0; t < KK / 4; ++t) {
            float4 v = pd[t];
            int4   w = pi[t];
            D[s][t * 4 + 0] = v.x; D[s][t * 4 + 1] = v.y;
            D[s][t * 4 + 2] = v.z; D[s][t * 4 + 3] = v.w;
            I[s][t * 4 + 0] = w.x; I[s][t * 4 + 1] = w.y;
            I[s][t * 4 + 2] = w.z; I[s][t * 4 + 3] = w.w;
        }
    }

    float m01[KK], m23[KK], fin[KK];
    int   j01[KK], j23[KK], jin[KK];
    merge16(D[0], I[0], D[1], I[1], m01, j01);
    merge16(D[2], I[2], D[3], I[3], m23, j23);
    merge16(m01, j01, m23, j23, fin, jin);

    const int set  = q / NPTS;
    const int base = set * NPTS;
    const size_t stride = (size_t)NQ * KK;

    float4* o_src = reinterpret_cast<float4*>(out + (size_t)q * KK);
    float4* o_dst = reinterpret_cast<float4*>(out + stride + (size_t)q * KK);
    float4* o_dis = reinterpret_cast<float4*>(out + 2 * stride + (size_t)q * KK);

    const float sv = (float)q;
#pragma unroll
    for (int t = 0; t < KK; t += 4) {
        o_src[t / 4] = make_float4(sv, sv, sv, sv);
        o_dst[t / 4] = make_float4((float)(base + jin[t + 0]),
                                   (float)(base + jin[t + 1]),
                                   (float)(base + jin[t + 2]),
                                   (float)(base + jin[t + 3]));
        o_dis[t / 4] = make_float4(fin[t + 0], fin[t + 1], fin[t + 2], fin[t + 3]);
    }
}

extern "C" void kernel_launch(void* const* d_in, const int* in_sizes, int n_in,
                              void* d_out, int out_size) {
    const float* x = (const float*)d_in[0];
    float* out = (float*)d_out;

    dim3 grid1(NPTS / QB, NSETS, SPLIT);
    knn_part<<<grid1, QT>>>(x);

    knn_merge<<<NQ / 128, 128>>>(out);
}

// round 11
// speedup vs baseline: 1.0767x; 1.0767x over previous
#include <cuda_runtime.h>

#define NSETS 8
#define NPTS  4096
#define DF    16
#define KK    16
#define QT    128                 // queries per block == threads per block
#define CT    128                 // candidate tile size
#define SPLIT 4                   // candidate-range splits (occupancy lever)
#define CPS   (NPTS / SPLIT)      // candidates per split = 1024
#define NQ    (NSETS * NPTS)      // total queries = 32768
#define BUFN  20                  // per-thread append buffer slots
#define FLUSH_AT 16               // flush when cnt >= 16 (4 slots slack, vote every 4)

typedef unsigned long long u64;
typedef unsigned int u32;

// ---- device scratch for partial top-k (no allocs allowed) ----
__device__ float g_partD[NQ * SPLIT * KK];
__device__ int   g_partI[NQ * SPLIT * KK];

// ---- packed f32x2 helpers (two fp32 lanes per instruction, exact) ----
__device__ __forceinline__ u64 f2mul(u64 a, u64 b) {
    u64 d; asm("mul.rn.f32x2 %0, %1, %2;" : "=l"(d) : "l"(a), "l"(b)); return d;
}
__device__ __forceinline__ u64 f2fma(u64 a, u64 b, u64 c) {
    u64 d; asm("fma.rn.f32x2 %0, %1, %2, %3;" : "=l"(d) : "l"(a), "l"(b), "l"(c)); return d;
}
__device__ __forceinline__ u64 f2add(u64 a, u64 b) {
    u64 d; asm("add.rn.f32x2 %0, %1, %2;" : "=l"(d) : "l"(a), "l"(b)); return d;
}

// 16-dim dot with a FIXED summation tree, used for norms AND cross dots so
// that self-distance cancels exactly: dot(q,q)==qn => fmaf(-2,dot,qn+cn)==0.
__device__ __forceinline__ float pdot16(const u64* a, const u64* b) {
    u64 pA = f2mul(a[0], b[0]);
    pA = f2fma(a[1], b[1], pA);
    pA = f2fma(a[2], b[2], pA);
    pA = f2fma(a[3], b[3], pA);
    u64 pB = f2mul(a[4], b[4]);
    pB = f2fma(a[5], b[5], pB);
    pB = f2fma(a[6], b[6], pB);
    pB = f2fma(a[7], b[7], pB);
    u64 pC = f2add(pA, pB);
    float lo, hi;
    asm("mov.b64 {%0, %1}, %2;" : "=f"(lo), "=f"(hi) : "l"(pC));
    return lo + hi;
}

// ============================ pass 1: partial top-k ============================
__global__ __launch_bounds__(QT) void knn_part(const float* __restrict__ x) {
    __shared__ ulonglong2 sC[CT * 4];     // candidate tile: 4x ulonglong2 per point
    __shared__ float      sN[CT];         // candidate squared norms
    __shared__ u64        sBuf[BUFN][QT]; // per-thread append buffers (conflict-free)

    const int set   = blockIdx.y;
    const int split = blockIdx.z;
    const int qi    = blockIdx.x * QT + threadIdx.x;
    const float* xs = x + (size_t)set * NPTS * DF;

    // shared address of this thread's buffer column (slot stride = QT*8 bytes)
    u32 sBufAddr;
    {
        u64 a64 = (u64)__cvta_generic_to_shared(&sBuf[0][threadIdx.x]);
        sBufAddr = (u32)a64;
    }

    // query point (packed) + its norm
    u64 q[8];
    {
        const ulonglong2* qp = reinterpret_cast<const ulonglong2*>(xs + (size_t)qi * DF);
        ulonglong2 w0 = qp[0], w1 = qp[1], w2 = qp[2], w3 = qp[3];
        q[0] = w0.x; q[1] = w0.y; q[2] = w1.x; q[3] = w1.y;
        q[4] = w2.x; q[5] = w2.y; q[6] = w3.x; q[7] = w3.y;
    }
    const float qn = pdot16(q, q);

    float bestD[KK];
    int   bestI[KK];
#pragma unroll
    for (int t = 0; t < KK; ++t) {
        bestD[t] = __int_as_float(0x7f800000);  // +inf
        bestI[t] = 0;
    }
    float threshD = __int_as_float(0x7f800000);
    int cnt = 0;

    // drain this thread's buffer into its sorted top-k (rare, warp-batched)
    auto flush = [&]() {
        for (int b = 0; b < cnt; ++b) {
            u64 key = sBuf[b][threadIdx.x];
            u32 iu; float d;
            asm("mov.b64 {%0, %1}, %2;" : "=r"(iu), "=f"(d) : "l"(key));
            if (d < bestD[KK - 1]) {   // re-check vs current (tighter) threshold
                const int idx = (int)iu;
#pragma unroll
                for (int t = KK - 1; t >= 1; --t) {
                    const bool shift = d < bestD[t - 1];
                    const bool here  = d < bestD[t];
                    bestD[t] = shift ? bestD[t - 1] : (here ? d : bestD[t]);
                    bestI[t] = shift ? bestI[t - 1] : (here ? idx : bestI[t]);
                }
                if (d < bestD[0]) { bestD[0] = d; bestI[0] = idx; }
            }
        }
        cnt = 0;
        threshD = bestD[KK - 1];
    };

    const int cbase = split * CPS;
    for (int tile = 0; tile < CPS / CT; ++tile) {
        const int cj0 = cbase + tile * CT;
        __syncthreads();
        {
            const ulonglong2* cp = reinterpret_cast<const ulonglong2*>(
                xs + (size_t)(cj0 + threadIdx.x) * DF);
            ulonglong2 w0 = cp[0], w1 = cp[1], w2 = cp[2], w3 = cp[3];
            sC[threadIdx.x * 4 + 0] = w0;
            sC[threadIdx.x * 4 + 1] = w1;
            sC[threadIdx.x * 4 + 2] = w2;
            sC[threadIdx.x * 4 + 3] = w3;
            u64 a[8] = {w0.x, w0.y, w1.x, w1.y, w2.x, w2.y, w3.x, w3.y};
            sN[threadIdx.x] = pdot16(a, a);
        }
        __syncthreads();

        for (int j0 = 0; j0 < CT; j0 += 4) {
            // 4 candidate norms in one LDS.128
            const float4 nv = reinterpret_cast<const float4*>(sN)[j0 / 4];
            const float cn[4] = {nv.x, nv.y, nv.z, nv.w};
#pragma unroll
            for (int u = 0; u < 4; ++u) {
                const int j = j0 + u;
                const ulonglong2* sp = &sC[j * 4];
                ulonglong2 w0 = sp[0], w1 = sp[1], w2 = sp[2], w3 = sp[3];
                u64 c[8] = {w0.x, w0.y, w1.x, w1.y, w2.x, w2.y, w3.x, w3.y};
                const float dot = pdot16(q, c);
                const float d = fmaf(-2.0f, dot, qn + cn[u]);
                const int idx = cj0 + j;
                u64 key;
                asm("mov.b64 %0, {%1, %2};" : "=l"(key) : "r"(idx), "f"(d));
                // branch-free predicated append: @p STS.64 (no BSSY, no traffic
                // on miss), predicated counter increment
                const u32 saddr = sBufAddr + (u32)cnt * (QT * 8);
                asm volatile(
                    "{\n\t"
                    ".reg .pred p;\n\t"
                    "setp.lt.f32 p, %1, %2;\n\t"
                    "@p st.shared.b64 [%0], %3;\n\t"
                    "}"
                    :: "r"(saddr), "f"(d), "f"(threshD), "l"(key) : "memory");
                cnt += (d < threshD) ? 1 : 0;
            }
            // warp-uniform check every 4 candidates (4 slots of buffer slack)
            if (__any_sync(0xffffffffu, cnt >= FLUSH_AT)) flush();
        }
    }
    if (__any_sync(0xffffffffu, cnt > 0)) flush();

    // write sorted partial list
    const int q_glob = set * NPTS + qi;
    float4* pd = reinterpret_cast<float4*>(&g_partD[((size_t)q_glob * SPLIT + split) * KK]);
    int4*   pi = reinterpret_cast<int4*>(&g_partI[((size_t)q_glob * SPLIT + split) * KK]);
#pragma unroll
    for (int t = 0; t < KK; t += 4) {
        pd[t / 4] = make_float4(bestD[t], bestD[t + 1], bestD[t + 2], bestD[t + 3]);
        pi[t / 4] = make_int4(bestI[t], bestI[t + 1], bestI[t + 2], bestI[t + 3]);
    }
}

// ============================ pass 2: merge + emit ============================
__device__ __forceinline__ bool lex_less(float d1, int i1, float d2, int i2) {
    return (d1 < d2) || (d1 == d2 && i1 < i2);
}

// merge two sorted-ascending 16-lists, keep the 16 smallest, result sorted.
__device__ __forceinline__ void merge16(const float* dA, const int* iA,
                                        const float* dB, const int* iB,
                                        float* dR, int* iR) {
#pragma unroll
    for (int i = 0; i < KK; ++i) {
        const bool ta = lex_less(dA[i], iA[i], dB[KK - 1 - i], iB[KK - 1 - i]);
        dR[i] = ta ? dA[i] : dB[KK - 1 - i];
        iR[i] = ta ? iA[i] : iB[KK - 1 - i];
    }
#pragma unroll
    for (int s = 8; s >= 1; s >>= 1) {
#pragma unroll
        for (int i = 0; i < KK; ++i) {
            if ((i & s) == 0) {
                const bool swap = !lex_less(dR[i], iR[i], dR[i + s], iR[i + s]);
                const float td = swap ? dR[i + s] : dR[i];
                const int   ti = swap ? iR[i + s] : iR[i];
                dR[i + s] = swap ? dR[i] : dR[i + s];
                iR[i + s] = swap ? iR[i] : iR[i + s];
                dR[i] = td;
                iR[i] = ti;
            }
        }
    }
}

__global__ __launch_bounds__(128) void knn_merge(float* __restrict__ out) {
    const int q = blockIdx.x * 128 + threadIdx.x;  // global query id
    if (q >= NQ) return;

    float D[SPLIT][KK];
    int   I[SPLIT][KK];
#pragma unroll
    for (int s = 0; s < SPLIT; ++s) {
        const float4* pd = reinterpret_cast<const float4*>(&g_partD[((size_t)q * SPLIT + s) * KK]);
        const int4*   pi = reinterpret_cast<const int4*>(&g_partI[((size_t)q * SPLIT + s) * KK]);
#pragma unroll
        for (int t = 0; t < KK / 4; ++t) {
            float4 v = pd[t];
            int4   w = pi[t];
            D[s][t * 4 + 0] = v.x; D[s][t * 4 + 1] = v.y;
            D[s][t * 4 + 2] = v.z; D[s][t * 4 + 3] = v.w;
            I[s][t * 4 + 0] = w.x; I[s][t * 4 + 1] = w.y;
            I[s][t * 4 + 2] = w.z; I[s][t * 4 + 3] = w.w;
        }
    }

    float m01[KK], m23[KK], fin[KK];
    int   j01[KK], j23[KK], jin[KK];
    merge16(D[0], I[0], D[1], I[1], m01, j01);
    merge16(D[2], I[2], D[3], I[3], m23, j23);
    merge16(m01, j01, m23, j23, fin, jin);

    const int set  = q / NPTS;
    const int base = set * NPTS;
    const size_t stride = (size_t)NQ * KK;

    float4* o_src = reinterpret_cast<float4*>(out + (size_t)q * KK);
    float4* o_dst = reinterpret_cast<float4*>(out + stride + (size_t)q * KK);
    float4* o_dis = reinterpret_cast<float4*>(out + 2 * stride + (size_t)q * KK);

    const float sv = (float)q;
#pragma unroll
    for (int t = 0; t < KK; t += 4) {
        o_src[t / 4] = make_float4(sv, sv, sv, sv);
        o_dst[t / 4] = make_float4((float)(base + jin[t + 0]),
                                   (float)(base + jin[t + 1]),
                                   (float)(base + jin[t + 2]),
                                   (float)(base + jin[t + 3]));
        o_dis[t / 4] = make_float4(fin[t + 0], fin[t + 1], fin[t + 2], fin[t + 3]);
    }
}

extern "C" void kernel_launch(void* const* d_in, const int* in_sizes, int n_in,
                              void* d_out, int out_size) {
    const float* x = (const float*)d_in[0];
    float* out = (float*)d_out;

    dim3 grid1(NPTS / QT, NSETS, SPLIT);
    knn_part<<<grid1, QT>>>(x);

    knn_merge<<<NQ / 128, 128>>>(out);
}